// round 7
// baseline (speedup 1.0000x reference)
#include <cuda_runtime.h>
#include <math.h>

// Problem constants
#define N_CAPS 64
#define CAPS_DIM 16
#define OUT_DIM 128
#define P_DIM 1152
#define BATCH 256
#define BO (BATCH * OUT_DIM)       // 32768
#define NCHUNK 24
#define PCHUNK (P_DIM / NCHUNK)    // 48
#define WROW 132                   // padded row stride (float4-aligned, conflict-free)

#define NB_RED 768                 // 32 colblks * 24 chunks
#define BID_WSUM 768
#define NB_ROUT 128                // 2 batch elems per routing block
#define NBLK (769 + NB_ROUT)       // 897

// Scratch (no cudaMalloc allowed)
__device__ __align__(16) float g_partial[NCHUNK * BO];     // 3 MB
__device__ __align__(16) float g_wsum[N_CAPS * OUT_DIM];   // [n][o], 32 KB
__device__ int g_cctr[33];   // [0..31] colblk done-count (target 24), [32] wsum flag
__device__ int g_done;       // routing blocks completed (target NB_ROUT)

// ---------------------------------------------------------------------------
// One fused persistent-style kernel.
//  bids 0..767  : x column-strip reduction (colblk-major so strips finish early)
//  bid  768     : Wsum[n,o] = sum_c w[n,c,o]
//  bids 769..896: routing, 2 batch elems per block; spin-waits on its colblk.
// Counters are reset by the last routing block (graph-replay safe).
// ---------------------------------------------------------------------------
__global__ void __launch_bounds__(256, 4) capsule_fused(
    const float4* __restrict__ x4,        // (1152, 256, 128) fp32 as float4
    const float4* __restrict__ w4,        // (64, 16, 128) fp32 as float4
    float* __restrict__ out)              // (256, 1, 128)
{
    const int bid = blockIdx.x;
    const int t   = threadIdx.x;

    // ---------------- x reduction blocks ----------------
    if (bid < NB_RED) {
        const int colblk = bid / NCHUNK;         // 0..31
        const int chunk  = bid % NCHUNK;         // 0..23
        const int col4   = colblk * 256 + t;     // float4 column index (0..8191)
        const float4* base = x4 + (size_t)(chunk * PCHUNK) * (BO / 4) + col4;

        float4 acc = make_float4(0.f, 0.f, 0.f, 0.f);
#pragma unroll 8
        for (int p = 0; p < PCHUNK; ++p) {
            float4 v = __ldcs(&base[(size_t)p * (BO / 4)]);
            acc.x += v.x; acc.y += v.y; acc.z += v.z; acc.w += v.w;
        }
        reinterpret_cast<float4*>(g_partial)[chunk * (BO / 4) + col4] = acc;

        __threadfence();
        __syncthreads();
        if (t == 0) atomicAdd(&g_cctr[colblk], 1);
        return;
    }

    // ---------------- wsum block ----------------
    if (bid == BID_WSUM) {
        for (int i4 = t; i4 < N_CAPS * (OUT_DIM / 4); i4 += 256) {
            int n  = i4 >> 5;
            int o4 = i4 & 31;
            const float4* base = w4 + (size_t)n * (CAPS_DIM * OUT_DIM / 4) + o4;
            float4 acc = make_float4(0.f, 0.f, 0.f, 0.f);
#pragma unroll
            for (int c = 0; c < CAPS_DIM; ++c) {
                float4 v = __ldg(&base[c * (OUT_DIM / 4)]);
                acc.x += v.x; acc.y += v.y; acc.z += v.z; acc.w += v.w;
            }
            reinterpret_cast<float4*>(g_wsum)[i4] = acc;
        }
        __threadfence();
        __syncthreads();
        if (t == 0) atomicAdd(&g_cctr[32], 1);
        return;
    }

    // ---------------- routing blocks ----------------
    const int r    = bid - 769;      // 0..127
    const int h    = t >> 7;         // half (batch within block)
    const int tt   = t & 127;        // o index
    const int lane = t & 31;
    const int wl   = (t >> 5) & 3;   // warp within half
    const int cblk = r >> 2;         // colblk this block depends on
    const int b    = r * 2 + h;      // batch element

    __shared__ __align__(16) float sh_w[N_CAPS * WROW];   // padded Wsum (33.8 KB)
    __shared__ __align__(16) float shrp[2][OUT_DIM];
    __shared__ float shpart[2][128];
    __shared__ float shc[2][N_CAPS];
    __shared__ float shred[2][4];

    // Wait for wsum, then stage W into shared
    if (t == 0) {
        volatile int* vc = g_cctr;
        while (vc[32] < 1) __nanosleep(64);
    }
    __syncthreads();
    __threadfence();
    for (int i4 = t; i4 < N_CAPS * (OUT_DIM / 4); i4 += 256) {
        float4 v = __ldg(&reinterpret_cast<const float4*>(g_wsum)[i4]);
        int n = i4 >> 5;
        int o = (i4 & 31) * 4;
        *reinterpret_cast<float4*>(&sh_w[n * WROW + o]) = v;
    }

    // Wait for our column strip's 24 partials
    if (t == 0) {
        volatile int* vc = g_cctr;
        while (vc[cblk] < NCHUNK) __nanosleep(64);
    }
    __syncthreads();
    __threadfence();

    // Finalize X[b, tt]
    float X = 0.f;
#pragma unroll
    for (int ch = 0; ch < NCHUNK; ++ch)
        X += g_partial[ch * BO + b * OUT_DIM + tt];

    if (tt < N_CAPS) shc[h][tt] = 1.0f / N_CAPS;
    float logit_a = 0.f, logit_b = 0.f;   // warp wl==0 of each half: caps lane, lane+32
    __syncthreads();

    float s, scale;
    for (int iter = 0; iter < 2; ++iter) {
        // s_o = X * sum_n c_n W[n,o]  (column LDS, conflict-free)
        s = 0.f;
#pragma unroll
        for (int n = 0; n < N_CAPS; ++n)
            s += shc[h][n] * sh_w[n * WROW + tt];
        s *= X;

        float sq = s * s;
#pragma unroll
        for (int off = 16; off > 0; off >>= 1)
            sq += __shfl_xor_sync(0xffffffffu, sq, off);
        if (lane == 0) shred[h][wl] = sq;
        __syncthreads();
        float tot = shred[h][0] + shred[h][1] + shred[h][2] + shred[h][3];
        scale = sqrtf(tot) / (1.0f + tot);         // norm / (1 + norm^2)

        shrp[h][tt] = scale * s * X;
        __syncthreads();

        // logits partial: thread tt -> cap (tt&63), o-half (tt>>6), float4 LDS
        {
            int n_id = tt & 63, oh = tt >> 6;
            const float4* wrow = reinterpret_cast<const float4*>(&sh_w[n_id * WROW]) + oh * 16;
            const float4* rp4  = reinterpret_cast<const float4*>(&shrp[h][0]) + oh * 16;
            float acc = 0.f;
#pragma unroll
            for (int j = 0; j < 16; ++j) {
                float4 wv = wrow[j], rv = rp4[j];
                acc += wv.x * rv.x + wv.y * rv.y + wv.z * rv.z + wv.w * rv.w;
            }
            shpart[h][tt] = acc;
        }
        __syncthreads();

        // first warp of each half: accumulate logits (2 caps/lane) + softmax
        if (wl == 0) {
            logit_a += shpart[h][lane]      + shpart[h][lane + 64];
            logit_b += shpart[h][lane + 32] + shpart[h][lane + 96];
            float m = fmaxf(logit_a, logit_b);
#pragma unroll
            for (int off = 16; off > 0; off >>= 1)
                m = fmaxf(m, __shfl_xor_sync(0xffffffffu, m, off));
            float ea = __expf(logit_a - m);
            float eb = __expf(logit_b - m);
            float sm = ea + eb;
#pragma unroll
            for (int off = 16; off > 0; off >>= 1)
                sm += __shfl_xor_sync(0xffffffffu, sm, off);
            float inv = 1.0f / sm;
            shc[h][lane]      = ea * inv;
            shc[h][lane + 32] = eb * inv;
        }
        __syncthreads();
    }

    // Final squash(coeffs @ xp)
    s = 0.f;
#pragma unroll
    for (int n = 0; n < N_CAPS; ++n)
        s += shc[h][n] * sh_w[n * WROW + tt];
    s *= X;
    float sq = s * s;
#pragma unroll
    for (int off = 16; off > 0; off >>= 1)
        sq += __shfl_xor_sync(0xffffffffu, sq, off);
    if (lane == 0) shred[h][wl] = sq;
    __syncthreads();
    float tot = shred[h][0] + shred[h][1] + shred[h][2] + shred[h][3];
    scale = sqrtf(tot) / (1.0f + tot);
    out[b * OUT_DIM + tt] = scale * s;

    // Done handshake + counter reset (graph-replay safe)
    __syncthreads();
    if (t == 0) {
        __threadfence();
        atomicAdd(&g_done, 1);
        if (bid == NBLK - 1) {
            volatile int* vd = &g_done;
            while (*vd < NB_ROUT) __nanosleep(64);
#pragma unroll
            for (int i = 0; i < 33; ++i) g_cctr[i] = 0;
            g_done = 0;
            __threadfence();
        }
    }
}

// ---------------------------------------------------------------------------
extern "C" void kernel_launch(void* const* d_in, const int* in_sizes, int n_in,
                              void* d_out, int out_size) {
    const float* x = (const float*)d_in[0];             // (1152, 256, 128)
    const float* w = (const float*)d_in[1];             // (64, 16, 128)
    float* out = (float*)d_out;                         // (256, 1, 128)

    capsule_fused<<<NBLK, 256>>>(reinterpret_cast<const float4*>(x),
                                 reinterpret_cast<const float4*>(w),
                                 out);
}

// round 8
// speedup vs baseline: 1.2338x; 1.2338x over previous
#include <cuda_runtime.h>
#include <math.h>

// Problem constants
#define N_CAPS 64
#define CAPS_DIM 16
#define OUT_DIM 128
#define P_DIM 1152
#define BATCH 256
#define BO (BATCH * OUT_DIM)       // 32768
#define PSPLIT 24
#define PCHUNK (P_DIM / PSPLIT)    // 48
#define WROW 132                   // padded row stride (float4-aligned, conflict-free)

// Scratch (no cudaMalloc allowed)
__device__ __align__(16) float g_partial[PSPLIT * BO];     // 3 MB
__device__ __align__(16) float g_wsum[N_CAPS * OUT_DIM];   // [n][o], 32 KB

// ---------------------------------------------------------------------------
// Kernel 1 (fused): grid (32, PSPLIT+1) x 256.
//  y < PSPLIT : X partials. x is (P, B, O) => matrix (P, 32768 floats).
//  y == PSPLIT: Wsum[n,o] = sum_c w[n,c,o] (float4), hidden inside the
//               HBM-bound reduction.
// ---------------------------------------------------------------------------
__global__ void __launch_bounds__(256) reduce_x_kernel(const float4* __restrict__ x4,
                                                       const float4* __restrict__ w4) {
    int chunk = blockIdx.y;

    if (chunk == PSPLIT) {
        int i = blockIdx.x * blockDim.x + threadIdx.x;   // float4 index into Wsum
        if (i >= N_CAPS * (OUT_DIM / 4)) return;
        int n  = i >> 5;                                 // 32 float4 per row
        int o4 = i & 31;
        const float4* base = w4 + (size_t)n * (CAPS_DIM * OUT_DIM / 4) + o4;
        float4 acc = make_float4(0.f, 0.f, 0.f, 0.f);
#pragma unroll
        for (int c = 0; c < CAPS_DIM; ++c) {
            float4 v = __ldg(&base[c * (OUT_DIM / 4)]);
            acc.x += v.x; acc.y += v.y; acc.z += v.z; acc.w += v.w;
        }
        reinterpret_cast<float4*>(g_wsum)[i] = acc;
        return;
    }

    int col = blockIdx.x * blockDim.x + threadIdx.x;     // 0..8191 (float4 units)
    const float4* base = x4 + (size_t)(chunk * PCHUNK) * (BO / 4) + col;

    float4 acc = make_float4(0.f, 0.f, 0.f, 0.f);
#pragma unroll 8
    for (int p = 0; p < PCHUNK; ++p) {
        float4 v = __ldcs(&base[(size_t)p * (BO / 4)]);
        acc.x += v.x; acc.y += v.y; acc.z += v.z; acc.w += v.w;
    }
    reinterpret_cast<float4*>(g_partial)[chunk * (BO / 4) + col] = acc;
}

// ---------------------------------------------------------------------------
// Kernel 2: routing. One block per batch element, 128 threads (thread t = o).
// W staged to shared in TWO phases (16 batched LDG -> 16 STS) so the L2
// latency is paid once (MLP=16), not 16 times.
// ---------------------------------------------------------------------------
__global__ void __launch_bounds__(128) routing_kernel(float* __restrict__ out) {
    const int b = blockIdx.x;
    const int t = threadIdx.x;
    const int lane = t & 31;
    const int wid  = t >> 5;
    const int n_id = t & 63;     // cap handled in logits phase
    const int half = t >> 6;     // o-half handled in logits phase

    __shared__ __align__(16) float sh_w[N_CAPS * WROW];   // padded Wsum (33.8 KB)
    __shared__ __align__(16) float shrp[OUT_DIM];         // rp vector
    __shared__ float shpart[128];                          // logits partials
    __shared__ float shc[N_CAPS];                          // coeffs
    __shared__ float shred[4];

    // ---- Phase A: batched independent loads (MLP-friendly) ----
    float4 wv[16];
    {
        const float4* w4 = reinterpret_cast<const float4*>(g_wsum);
#pragma unroll
        for (int k = 0; k < 16; ++k)
            wv[k] = __ldg(&w4[t + k * 128]);
    }

    // X finalize: 24 independent loads (overlap with W loads in flight)
    float X = 0.f;
#pragma unroll
    for (int ch = 0; ch < PSPLIT; ++ch)
        X += g_partial[ch * BO + b * OUT_DIM + t];

    // ---- Phase B: store W to padded shared ----
#pragma unroll
    for (int k = 0; k < 16; ++k) {
        int i4 = t + k * 128;
        int n  = i4 >> 5;
        int o  = (i4 & 31) * 4;
        *reinterpret_cast<float4*>(&sh_w[n * WROW + o]) = wv[k];
    }

    if (t < N_CAPS) shc[t] = 1.0f / N_CAPS;
    float logit_a = 0.f, logit_b = 0.f;     // warp 0: caps lane, lane+32
    __syncthreads();

    // ITERATIONS = 3 -> 2 routing updates, then final squash
    for (int iter = 0; iter < 3; ++iter) {
        // s_o = X * sum_n c_n * W[n,o]   (column LDS, lanes consecutive)
        float s = 0.f;
#pragma unroll
        for (int n = 0; n < N_CAPS; ++n)
            s += shc[n] * sh_w[n * WROW + t];
        s *= X;

        // block reduce ||s||^2
        float sq = s * s;
#pragma unroll
        for (int off = 16; off > 0; off >>= 1)
            sq += __shfl_xor_sync(0xffffffffu, sq, off);
        if (lane == 0) shred[wid] = sq;
        __syncthreads();
        float tot   = shred[0] + shred[1] + shred[2] + shred[3];
        float scale = sqrtf(tot) / (1.0f + tot);   // norm / (1 + norm^2)

        if (iter == 2) {
            out[b * OUT_DIM + t] = scale * s;      // final squash(coeffs @ xp)
            return;
        }

        // rp to shared
        shrp[t] = scale * s * X;
        __syncthreads();

        // logits partial: thread t -> cap n_id, o-half "half" (float4 LDS rows)
        {
            const float4* wrow = reinterpret_cast<const float4*>(&sh_w[n_id * WROW]) + half * 16;
            const float4* rp4  = reinterpret_cast<const float4*>(shrp) + half * 16;
            float acc = 0.f;
#pragma unroll
            for (int j = 0; j < 16; ++j) {
                float4 w4v = wrow[j];
                float4 r4v = rp4[j];
                acc += w4v.x * r4v.x + w4v.y * r4v.y + w4v.z * r4v.z + w4v.w * r4v.w;
            }
            shpart[t] = acc;    // [half*64 + n]
        }
        __syncthreads();

        // warp 0: accumulate logits (2 caps/lane) + softmax fully in-warp
        if (wid == 0) {
            logit_a += shpart[lane]      + shpart[lane + 64];
            logit_b += shpart[lane + 32] + shpart[lane + 96];
            float m = fmaxf(logit_a, logit_b);
#pragma unroll
            for (int off = 16; off > 0; off >>= 1)
                m = fmaxf(m, __shfl_xor_sync(0xffffffffu, m, off));
            float ea = __expf(logit_a - m);
            float eb = __expf(logit_b - m);
            float sm = ea + eb;
#pragma unroll
            for (int off = 16; off > 0; off >>= 1)
                sm += __shfl_xor_sync(0xffffffffu, sm, off);
            float inv = 1.0f / sm;
            shc[lane]      = ea * inv;
            shc[lane + 32] = eb * inv;
        }
        __syncthreads();
    }
}

// ---------------------------------------------------------------------------
extern "C" void kernel_launch(void* const* d_in, const int* in_sizes, int n_in,
                              void* d_out, int out_size) {
    const float* x = (const float*)d_in[0];             // (1152, 256, 128)
    const float* w = (const float*)d_in[1];             // (64, 16, 128)
    float* out = (float*)d_out;                         // (256, 1, 128)

    dim3 g1(32, PSPLIT + 1);
    reduce_x_kernel<<<g1, 256>>>(reinterpret_cast<const float4*>(x),
                                 reinterpret_cast<const float4*>(w));
    routing_kernel<<<BATCH, 128>>>(out);
}

// round 9
// speedup vs baseline: 1.2602x; 1.0214x over previous
#include <cuda_runtime.h>
#include <math.h>

// Problem constants
#define N_CAPS 64
#define CAPS_DIM 16
#define OUT_DIM 128
#define P_DIM 1152
#define BATCH 256
#define BO (BATCH * OUT_DIM)       // 32768
#define PSPLIT 24
#define PCHUNK (P_DIM / PSPLIT)    // 48
#define WROW 132                   // padded row stride (float4-aligned, conflict-free)

// Scratch (no cudaMalloc allowed)
__device__ __align__(16) float g_partial[PSPLIT * BO];     // 3 MB
__device__ __align__(16) float g_wsum[N_CAPS * OUT_DIM];   // [n][o], 32 KB

// ---------------------------------------------------------------------------
// Kernel 1 (fused): grid (32, PSPLIT+1) x 256.
//  y < PSPLIT : X partials. x is (P, B, O) => matrix (P, 32768 floats).
//  y == PSPLIT: Wsum[n,o] = sum_c w[n,c,o] (float4), hidden inside the
//               HBM-bound reduction.
// ---------------------------------------------------------------------------
__global__ void __launch_bounds__(256) reduce_x_kernel(const float4* __restrict__ x4,
                                                       const float4* __restrict__ w4) {
    int chunk = blockIdx.y;

    if (chunk == PSPLIT) {
        int i = blockIdx.x * blockDim.x + threadIdx.x;   // float4 index into Wsum
        if (i >= N_CAPS * (OUT_DIM / 4)) return;
        int n  = i >> 5;                                 // 32 float4 per row
        int o4 = i & 31;
        const float4* base = w4 + (size_t)n * (CAPS_DIM * OUT_DIM / 4) + o4;
        float4 acc = make_float4(0.f, 0.f, 0.f, 0.f);
#pragma unroll
        for (int c = 0; c < CAPS_DIM; ++c) {
            float4 v = __ldg(&base[c * (OUT_DIM / 4)]);
            acc.x += v.x; acc.y += v.y; acc.z += v.z; acc.w += v.w;
        }
        reinterpret_cast<float4*>(g_wsum)[i] = acc;
        return;
    }

    int col = blockIdx.x * blockDim.x + threadIdx.x;     // 0..8191 (float4 units)
    const float4* base = x4 + (size_t)(chunk * PCHUNK) * (BO / 4) + col;

    float4 acc = make_float4(0.f, 0.f, 0.f, 0.f);
#pragma unroll 8
    for (int p = 0; p < PCHUNK; ++p) {
        float4 v = __ldcs(&base[(size_t)p * (BO / 4)]);
        acc.x += v.x; acc.y += v.y; acc.z += v.z; acc.w += v.w;
    }
    reinterpret_cast<float4*>(g_partial)[chunk * (BO / 4) + col] = acc;
}

// ---------------------------------------------------------------------------
// Kernel 2: routing. 128 blocks x 256 threads, 2 batch elems per block
// (single wave: 1 block/SM, 8 warps for latency hiding).
//   half h = t>>7 owns batch b = 2*blockIdx.x + h; tt = t&127 is the o index.
//   sh_w staged once, shared by both halves.
// ---------------------------------------------------------------------------
__global__ void __launch_bounds__(256) routing_kernel(float* __restrict__ out) {
    const int t    = threadIdx.x;
    const int h    = t >> 7;         // batch half within block
    const int tt   = t & 127;        // o index
    const int lane = t & 31;
    const int wl   = (t >> 5) & 3;   // warp within half
    const int b    = blockIdx.x * 2 + h;

    __shared__ __align__(16) float sh_w[N_CAPS * WROW];   // padded Wsum (33.8 KB)
    __shared__ __align__(16) float shrp[2][OUT_DIM];
    __shared__ float shpart[2][128];
    __shared__ float shc[2][N_CAPS];
    __shared__ float shred[2][4];

    // ---- Phase A: batched independent W loads (8 float4/thread, MLP=8) ----
    float4 wv[8];
    {
        const float4* w4 = reinterpret_cast<const float4*>(g_wsum);
#pragma unroll
        for (int k = 0; k < 8; ++k)
            wv[k] = __ldg(&w4[t + k * 256]);
    }

    // X finalize: 24 independent loads (in flight together with W loads)
    float X = 0.f;
#pragma unroll
    for (int ch = 0; ch < PSPLIT; ++ch)
        X += g_partial[ch * BO + b * OUT_DIM + tt];

    // ---- Phase B: store W to padded shared ----
#pragma unroll
    for (int k = 0; k < 8; ++k) {
        int i4 = t + k * 256;
        int n  = i4 >> 5;
        int o  = (i4 & 31) * 4;
        *reinterpret_cast<float4*>(&sh_w[n * WROW + o]) = wv[k];
    }

    if (tt < N_CAPS) shc[h][tt] = 1.0f / N_CAPS;
    float logit_a = 0.f, logit_b = 0.f;     // per-half warp 0: caps lane, lane+32
    __syncthreads();

    // ITERATIONS = 3 -> 2 routing updates, then final squash
    for (int iter = 0; iter < 3; ++iter) {
        // s_o = X * sum_n c_n * W[n,o]   (column LDS, lanes consecutive)
        float s = 0.f;
#pragma unroll
        for (int n = 0; n < N_CAPS; ++n)
            s += shc[h][n] * sh_w[n * WROW + tt];
        s *= X;

        // reduce ||s||^2 over the 128 threads of this half
        float sq = s * s;
#pragma unroll
        for (int off = 16; off > 0; off >>= 1)
            sq += __shfl_xor_sync(0xffffffffu, sq, off);
        if (lane == 0) shred[h][wl] = sq;
        __syncthreads();
        float tot   = shred[h][0] + shred[h][1] + shred[h][2] + shred[h][3];
        float scale = sqrtf(tot) / (1.0f + tot);   // norm / (1 + norm^2)

        if (iter == 2) {
            out[b * OUT_DIM + tt] = scale * s;     // final squash(coeffs @ xp)
            return;
        }

        // rp to shared
        shrp[h][tt] = scale * s * X;
        __syncthreads();

        // logits partial: thread tt -> cap (tt&63), o-half (tt>>6), float4 LDS
        {
            int n_id = tt & 63, oh = tt >> 6;
            const float4* wrow = reinterpret_cast<const float4*>(&sh_w[n_id * WROW]) + oh * 16;
            const float4* rp4  = reinterpret_cast<const float4*>(&shrp[h][0]) + oh * 16;
            float acc = 0.f;
#pragma unroll
            for (int j = 0; j < 16; ++j) {
                float4 w4v = wrow[j];
                float4 r4v = rp4[j];
                acc += w4v.x * r4v.x + w4v.y * r4v.y + w4v.z * r4v.z + w4v.w * r4v.w;
            }
            shpart[h][tt] = acc;    // [oh*64 + n]
        }
        __syncthreads();

        // per-half first warp: accumulate logits (2 caps/lane) + softmax
        if (wl == 0) {
            logit_a += shpart[h][lane]      + shpart[h][lane + 64];
            logit_b += shpart[h][lane + 32] + shpart[h][lane + 96];
            float m = fmaxf(logit_a, logit_b);
#pragma unroll
            for (int off = 16; off > 0; off >>= 1)
                m = fmaxf(m, __shfl_xor_sync(0xffffffffu, m, off));
            float ea = __expf(logit_a - m);
            float eb = __expf(logit_b - m);
            float sm = ea + eb;
#pragma unroll
            for (int off = 16; off > 0; off >>= 1)
                sm += __shfl_xor_sync(0xffffffffu, sm, off);
            float inv = 1.0f / sm;
            shc[h][lane]      = ea * inv;
            shc[h][lane + 32] = eb * inv;
        }
        __syncthreads();
    }
}

// ---------------------------------------------------------------------------
extern "C" void kernel_launch(void* const* d_in, const int* in_sizes, int n_in,
                              void* d_out, int out_size) {
    const float* x = (const float*)d_in[0];             // (1152, 256, 128)
    const float* w = (const float*)d_in[1];             // (64, 16, 128)
    float* out = (float*)d_out;                         // (256, 1, 128)

    dim3 g1(32, PSPLIT + 1);
    reduce_x_kernel<<<g1, 256>>>(reinterpret_cast<const float4*>(x),
                                 reinterpret_cast<const float4*>(w));
    routing_kernel<<<BATCH / 2, 256>>>(out);
}